// round 4
// baseline (speedup 1.0000x reference)
#include <cuda_runtime.h>
#include <cstdint>

// ============================================================================
// Problem constants
// ============================================================================
#define DIM     4096
#define BS      128
#define KBLK    32

// GEMM tiling
#define TILE_M  128
#define TILE_N  128
#define TILE_K  32
#define STAGES  4
#define KSTEPS  (DIM / TILE_K)      // 128

#define SMA_STRIDE 36               // 32 + 4 pad floats: conflict-free frag loads
#define A_STAGE_FLOATS (TILE_M * SMA_STRIDE)   // 4608
#define B_STAGE_FLOATS (TILE_N * SMA_STRIDE)   // 4608
#define SMEM_TOTAL ((STAGES * (A_STAGE_FLOATS + B_STAGE_FLOATS)) * 4)  // 147456 B

static_assert(SMEM_TOTAL <= 227 * 1024, "smem over per-CTA limit");

// ============================================================================
// Scratch (device globals; no runtime allocation)
// ============================================================================
__device__ __align__(1024) float g_A[(size_t)DIM * DIM];   // x * D, tf32-rounded
__device__ __align__(1024) float g_B[(size_t)DIM * DIM];   // circulant M, tf32-rounded

// ============================================================================
// Helpers
// ============================================================================
// cvt.rna.tf32.f32 requires a b32 (integer) destination register.
__device__ __forceinline__ float tf32_rn(float v) {
    uint32_t r;
    asm("cvt.rna.tf32.f32 %0, %1;" : "=r"(r) : "f"(v));
    return __uint_as_float(r);
}

__device__ __forceinline__ uint32_t smem_u32(const void* p) {
    uint32_t a;
    asm("{ .reg .u64 t; cvta.to.shared.u64 t, %1; cvt.u32.u64 %0, t; }" : "=r"(a) : "l"(p));
    return a;
}

#define CP_ASYNC16(smem_addr, gptr) \
    asm volatile("cp.async.cg.shared.global [%0], [%1], 16;" \
                 :: "r"(smem_addr), "l"(gptr) : "memory")
#define CP_COMMIT() asm volatile("cp.async.commit_group;" ::: "memory")
#define CP_WAIT(n)  asm volatile("cp.async.wait_group %0;" :: "n"(n) : "memory")

__device__ __forceinline__ void mma_tf32(
    float& c0, float& c1, float& c2, float& c3,
    uint32_t a0, uint32_t a1, uint32_t a2, uint32_t a3,
    uint32_t b0, uint32_t b1)
{
    asm volatile(
        "mma.sync.aligned.m16n8k8.row.col.f32.tf32.tf32.f32 "
        "{%0,%1,%2,%3}, {%4,%5,%6,%7}, {%8,%9}, {%0,%1,%2,%3};"
        : "+f"(c0), "+f"(c1), "+f"(c2), "+f"(c3)
        : "r"(a0), "r"(a1), "r"(a2), "r"(a3), "r"(b0), "r"(b1));
}

// ============================================================================
// Prep kernels
// ============================================================================
// A[b, k] = tf32(x[b, k] * D[k])
__global__ void __launch_bounds__(256) prep_a_kernel(
    const float* __restrict__ x, const float* __restrict__ D, float* __restrict__ A)
{
    int i4 = blockIdx.x * blockDim.x + threadIdx.x;
    float4 xv = reinterpret_cast<const float4*>(x)[i4];
    float4 dv = reinterpret_cast<const float4*>(D)[i4 & 1023];
    float4 v;
    v.x = tf32_rn(xv.x * dv.x);
    v.y = tf32_rn(xv.y * dv.y);
    v.z = tf32_rn(xv.z * dv.z);
    v.w = tf32_rn(xv.w * dv.w);
    reinterpret_cast<float4*>(A)[i4] = v;
}

// Bm[o, in] = tf32(W[o>>7, in>>7, (in - o) & 127])
__global__ void __launch_bounds__(256) prep_b_kernel(
    const float* __restrict__ W, float* __restrict__ Bm)
{
    int i4 = blockIdx.x * blockDim.x + threadIdx.x;
    int o  = i4 >> 10;
    int ub = (i4 & 1023) << 2;
    int i  = o >> 7;
    int t  = o & 127;
    int j  = ub >> 7;
    int u  = ub & 127;
    const float* wrow = W + ((size_t)((i << 5) + j) << 7);
    float4 v;
    v.x = tf32_rn(__ldg(&wrow[(u     - t) & 127]));
    v.y = tf32_rn(__ldg(&wrow[(u + 1 - t) & 127]));
    v.z = tf32_rn(__ldg(&wrow[(u + 2 - t) & 127]));
    v.w = tf32_rn(__ldg(&wrow[(u + 3 - t) & 127]));
    reinterpret_cast<float4*>(Bm)[i4] = v;
}

// ============================================================================
// TF32 GEMM: out[4096,4096] = A @ Bm^T + bias
// 128x128x32 CTA tile, 256 threads, 8 warps (2m x 4n, warp tile 64x32),
// mma.sync.m16n8k8.tf32, 4-stage cp.async pipeline.
// ============================================================================
__global__ void __launch_bounds__(256, 1) gemm_tf32_kernel(
    const float* __restrict__ A, const float* __restrict__ Bm,
    const float* __restrict__ bias, float* __restrict__ out)
{
    extern __shared__ __align__(128) float smem[];
    float* As = smem;
    float* Bs = smem + STAGES * A_STAGE_FLOATS;

    const int tid  = threadIdx.x;
    const int lane = tid & 31;
    const int wid  = tid >> 5;
    const int warp_m = wid & 1;       // 0..1
    const int warp_n = wid >> 1;      // 0..3
    const int wm = warp_m * 64;
    const int wn = warp_n * 32;

    // m fastest in grid -> a wave shares B panels in L2
    const int m_t = blockIdx.x & 31;
    const int n_t = blockIdx.x >> 5;
    const int m_base = m_t * TILE_M;
    const int n_base = n_t * TILE_N;

    // ---- cp.async mapping: thread t loads 4 float4s of one row half ----
    const int ld_row  = tid >> 1;           // 0..127
    const int ld_half = (tid & 1) * 4;      // f4 col base 0 or 4
    const float* gA = A  + (size_t)(m_base + ld_row) * DIM + ld_half * 4;
    const float* gB = Bm + (size_t)(n_base + ld_row) * DIM + ld_half * 4;
    const uint32_t sA_w = smem_u32(As) + (ld_row * SMA_STRIDE + ld_half * 4) * 4;
    const uint32_t sB_w = smem_u32(Bs) + (ld_row * SMA_STRIDE + ld_half * 4) * 4;

    // ---- fragment read bases ----
    const int row_a = wm + (lane >> 2);
    const int row_b = wn + (lane >> 2);
    const int col_f = lane & 3;

    float c[4][4][4];
    #pragma unroll
    for (int mi = 0; mi < 4; mi++)
        #pragma unroll
        for (int ni = 0; ni < 4; ni++)
            #pragma unroll
            for (int q = 0; q < 4; q++) c[mi][ni][q] = 0.0f;

    // ---- prologue: fill STAGES-1 stages ----
    #pragma unroll
    for (int s = 0; s < STAGES - 1; s++) {
        const size_t gk = (size_t)s * TILE_K;
        #pragma unroll
        for (int i = 0; i < 4; i++) {
            CP_ASYNC16(sA_w + (s * A_STAGE_FLOATS + i * 4) * 4, gA + gk + i * 4);
            CP_ASYNC16(sB_w + (s * B_STAGE_FLOATS + i * 4) * 4, gB + gk + i * 4);
        }
        CP_COMMIT();
    }

    // ---- mainloop ----
    for (int ks = 0; ks < KSTEPS; ks++) {
        CP_WAIT(STAGES - 2);
        __syncthreads();

        // issue next stage load
        {
            const int ksn = ks + STAGES - 1;
            if (ksn < KSTEPS) {
                const int s = ksn & (STAGES - 1);
                const size_t gk = (size_t)ksn * TILE_K;
                #pragma unroll
                for (int i = 0; i < 4; i++) {
                    CP_ASYNC16(sA_w + (s * A_STAGE_FLOATS + i * 4) * 4, gA + gk + i * 4);
                    CP_ASYNC16(sB_w + (s * B_STAGE_FLOATS + i * 4) * 4, gB + gk + i * 4);
                }
            }
            CP_COMMIT();
        }

        const int s = ks & (STAGES - 1);
        const uint32_t* Af = reinterpret_cast<const uint32_t*>(As + s * A_STAGE_FLOATS);
        const uint32_t* Bf = reinterpret_cast<const uint32_t*>(Bs + s * B_STAGE_FLOATS);

        #pragma unroll
        for (int kk = 0; kk < TILE_K / 8; kk++) {
            uint32_t a[4][4];
            #pragma unroll
            for (int mi = 0; mi < 4; mi++) {
                const uint32_t* p = Af + (row_a + mi * 16) * SMA_STRIDE + kk * 8 + col_f;
                a[mi][0] = p[0];
                a[mi][1] = p[8 * SMA_STRIDE];
                a[mi][2] = p[4];
                a[mi][3] = p[8 * SMA_STRIDE + 4];
            }
            uint32_t b[4][2];
            #pragma unroll
            for (int ni = 0; ni < 4; ni++) {
                const uint32_t* p = Bf + (row_b + ni * 8) * SMA_STRIDE + kk * 8 + col_f;
                b[ni][0] = p[0];
                b[ni][1] = p[4];
            }
            #pragma unroll
            for (int mi = 0; mi < 4; mi++)
                #pragma unroll
                for (int ni = 0; ni < 4; ni++)
                    mma_tf32(c[mi][ni][0], c[mi][ni][1], c[mi][ni][2], c[mi][ni][3],
                             a[mi][0], a[mi][1], a[mi][2], a[mi][3],
                             b[ni][0], b[ni][1]);
        }
        __syncthreads();
    }

    // ---- epilogue: bias + store ----
    float2 bv[4];
    #pragma unroll
    for (int ni = 0; ni < 4; ni++) {
        const int cb = n_base + wn + ni * 8 + (lane & 3) * 2;
        bv[ni].x = __ldg(&bias[cb]);
        bv[ni].y = __ldg(&bias[cb + 1]);
    }
    #pragma unroll
    for (int mi = 0; mi < 4; mi++) {
        const int r0 = m_base + wm + mi * 16 + (lane >> 2);
        #pragma unroll
        for (int ni = 0; ni < 4; ni++) {
            const int cb = n_base + wn + ni * 8 + (lane & 3) * 2;
            float2 v0 = make_float2(c[mi][ni][0] + bv[ni].x, c[mi][ni][1] + bv[ni].y);
            float2 v1 = make_float2(c[mi][ni][2] + bv[ni].x, c[mi][ni][3] + bv[ni].y);
            *reinterpret_cast<float2*>(out + (size_t)r0 * DIM + cb)       = v0;
            *reinterpret_cast<float2*>(out + (size_t)(r0 + 8) * DIM + cb) = v1;
        }
    }
}

// ============================================================================
// Host launcher
// ============================================================================
extern "C" void kernel_launch(void* const* d_in, const int* in_sizes, int n_in,
                              void* d_out, int out_size)
{
    const float* x = nullptr;
    const float* W = nullptr;
    const float* D = nullptr;
    const float* bias = nullptr;
    for (int i = 0; i < n_in; i++) {
        if (in_sizes[i] == DIM * DIM)              x = (const float*)d_in[i];
        else if (in_sizes[i] == KBLK * KBLK * BS)  W = (const float*)d_in[i];
        else if (!D)                               D = (const float*)d_in[i];
        else                                       bias = (const float*)d_in[i];
    }
    float* out = (float*)d_out;

    float* dA = nullptr;
    float* dB = nullptr;
    cudaGetSymbolAddress((void**)&dA, g_A);
    cudaGetSymbolAddress((void**)&dB, g_B);

    prep_a_kernel<<<(DIM * DIM / 4) / 256, 256>>>(x, D, dA);
    prep_b_kernel<<<(DIM * DIM / 4) / 256, 256>>>(W, dB);

    cudaFuncSetAttribute(gemm_tf32_kernel,
                         cudaFuncAttributeMaxDynamicSharedMemorySize, SMEM_TOTAL);

    const int grid = (DIM / TILE_M) * (DIM / TILE_N);   // 32 * 32 = 1024
    gemm_tf32_kernel<<<grid, 256, SMEM_TOTAL>>>(dA, dB, bias, out);
}

// round 5
// speedup vs baseline: 1.0886x; 1.0886x over previous
#include <cuda_runtime.h>
#include <cstdint>

// ============================================================================
// Problem constants
// ============================================================================
#define DIM     4096
#define BS      128
#define KBLK    32

// GEMM tiling
#define TILE_M  128
#define TILE_N  128
#define TILE_K  32
#define STAGES  3
#define KSTEPS  (DIM / TILE_K)      // 128

#define SMA_STRIDE 36               // 32 + 4 pad floats: conflict-free frag loads
#define A_STAGE_FLOATS (TILE_M * SMA_STRIDE)   // 4608
#define B_STAGE_FLOATS (TILE_N * SMA_STRIDE)   // 4608
#define SMEM_TOTAL ((STAGES * (A_STAGE_FLOATS + B_STAGE_FLOATS)) * 4)  // 110592 B

static_assert(2 * SMEM_TOTAL <= 227 * 1024, "want 2 CTAs per SM");

// ============================================================================
// Scratch (device globals; no runtime allocation)
// ============================================================================
__device__ __align__(1024) float g_A[(size_t)DIM * DIM];   // x * D, tf32-rounded
__device__ __align__(1024) float g_B[(size_t)DIM * DIM];   // circulant M, tf32-rounded

// ============================================================================
// Helpers
// ============================================================================
// cvt.rna.tf32.f32 requires a b32 (integer) destination register.
__device__ __forceinline__ float tf32_rn(float v) {
    uint32_t r;
    asm("cvt.rna.tf32.f32 %0, %1;" : "=r"(r) : "f"(v));
    return __uint_as_float(r);
}

__device__ __forceinline__ uint32_t smem_u32(const void* p) {
    uint32_t a;
    asm("{ .reg .u64 t; cvta.to.shared.u64 t, %1; cvt.u32.u64 %0, t; }" : "=r"(a) : "l"(p));
    return a;
}

#define CP_ASYNC16(smem_addr, gptr) \
    asm volatile("cp.async.cg.shared.global [%0], [%1], 16;" \
                 :: "r"(smem_addr), "l"(gptr) : "memory")
#define CP_COMMIT() asm volatile("cp.async.commit_group;" ::: "memory")
#define CP_WAIT(n)  asm volatile("cp.async.wait_group %0;" :: "n"(n) : "memory")

__device__ __forceinline__ void mma_tf32(
    float& c0, float& c1, float& c2, float& c3,
    uint32_t a0, uint32_t a1, uint32_t a2, uint32_t a3,
    uint32_t b0, uint32_t b1)
{
    asm volatile(
        "mma.sync.aligned.m16n8k8.row.col.f32.tf32.tf32.f32 "
        "{%0,%1,%2,%3}, {%4,%5,%6,%7}, {%8,%9}, {%0,%1,%2,%3};"
        : "+f"(c0), "+f"(c1), "+f"(c2), "+f"(c3)
        : "r"(a0), "r"(a1), "r"(a2), "r"(a3), "r"(b0), "r"(b1));
}

// ============================================================================
// Prep kernels
// ============================================================================
// A[b, k] = tf32(x[b, k] * D[k])
__global__ void __launch_bounds__(256) prep_a_kernel(
    const float* __restrict__ x, const float* __restrict__ D, float* __restrict__ A)
{
    int i4 = blockIdx.x * blockDim.x + threadIdx.x;
    float4 xv = reinterpret_cast<const float4*>(x)[i4];
    float4 dv = reinterpret_cast<const float4*>(D)[i4 & 1023];
    float4 v;
    v.x = tf32_rn(xv.x * dv.x);
    v.y = tf32_rn(xv.y * dv.y);
    v.z = tf32_rn(xv.z * dv.z);
    v.w = tf32_rn(xv.w * dv.w);
    reinterpret_cast<float4*>(A)[i4] = v;
}

// Bm[o, in] = tf32(W[o>>7, in>>7, (in - o) & 127])
__global__ void __launch_bounds__(256) prep_b_kernel(
    const float* __restrict__ W, float* __restrict__ Bm)
{
    int i4 = blockIdx.x * blockDim.x + threadIdx.x;
    int o  = i4 >> 10;
    int ub = (i4 & 1023) << 2;
    int i  = o >> 7;
    int t  = o & 127;
    int j  = ub >> 7;
    int u  = ub & 127;
    const float* wrow = W + ((size_t)((i << 5) + j) << 7);
    float4 v;
    v.x = tf32_rn(__ldg(&wrow[(u     - t) & 127]));
    v.y = tf32_rn(__ldg(&wrow[(u + 1 - t) & 127]));
    v.z = tf32_rn(__ldg(&wrow[(u + 2 - t) & 127]));
    v.w = tf32_rn(__ldg(&wrow[(u + 3 - t) & 127]));
    reinterpret_cast<float4*>(Bm)[i4] = v;
}

// ============================================================================
// TF32 GEMM: out[4096,4096] = A @ Bm^T + bias
// 128x128x32 CTA tile, 256 threads, 8 warps (2m x 4n, warp tile 64x32),
// mma.sync.m16n8k8.tf32, 3-stage cp.async pipeline, 2 CTAs/SM,
// single __syncthreads per k-step.
// ============================================================================
__global__ void __launch_bounds__(256, 2) gemm_tf32_kernel(
    const float* __restrict__ A, const float* __restrict__ Bm,
    const float* __restrict__ bias, float* __restrict__ out)
{
    extern __shared__ __align__(128) float smem[];
    float* As = smem;
    float* Bs = smem + STAGES * A_STAGE_FLOATS;

    const int tid  = threadIdx.x;
    const int lane = tid & 31;
    const int wid  = tid >> 5;
    const int warp_m = wid & 1;       // 0..1
    const int warp_n = wid >> 1;      // 0..3
    const int wm = warp_m * 64;
    const int wn = warp_n * 32;

    // m fastest in grid -> a wave shares B panels in L2
    const int m_t = blockIdx.x & 31;
    const int n_t = blockIdx.x >> 5;
    const int m_base = m_t * TILE_M;
    const int n_base = n_t * TILE_N;

    // ---- cp.async mapping: thread t loads 4 float4s of one row half ----
    const int ld_row  = tid >> 1;           // 0..127
    const int ld_half = (tid & 1) * 4;      // f4 col base 0 or 4
    const float* gA = A  + (size_t)(m_base + ld_row) * DIM + ld_half * 4;
    const float* gB = Bm + (size_t)(n_base + ld_row) * DIM + ld_half * 4;
    const uint32_t sA_w = smem_u32(As) + (ld_row * SMA_STRIDE + ld_half * 4) * 4;
    const uint32_t sB_w = smem_u32(Bs) + (ld_row * SMA_STRIDE + ld_half * 4) * 4;

    // ---- fragment read bases ----
    const int row_a = wm + (lane >> 2);
    const int row_b = wn + (lane >> 2);
    const int col_f = lane & 3;

    float c[4][4][4];
    #pragma unroll
    for (int mi = 0; mi < 4; mi++)
        #pragma unroll
        for (int ni = 0; ni < 4; ni++)
            #pragma unroll
            for (int q = 0; q < 4; q++) c[mi][ni][q] = 0.0f;

    // ---- prologue: fill STAGES-1 stages ----
    #pragma unroll
    for (int s = 0; s < STAGES - 1; s++) {
        const size_t gk = (size_t)s * TILE_K;
        #pragma unroll
        for (int i = 0; i < 4; i++) {
            CP_ASYNC16(sA_w + (s * A_STAGE_FLOATS + i * 4) * 4, gA + gk + i * 4);
            CP_ASYNC16(sB_w + (s * B_STAGE_FLOATS + i * 4) * 4, gB + gk + i * 4);
        }
        CP_COMMIT();
    }

    // ---- mainloop: ONE barrier per k-step ----
    int sw = STAGES - 1;    // stage to write next
    int sr = 0;             // stage to read
    for (int ks = 0; ks < KSTEPS; ks++) {
        CP_WAIT(STAGES - 2);
        __syncthreads();
        // After this barrier: stage sr is resident, and every thread has
        // finished reading stage sw (it was read STAGES-1 iters ago), so
        // overwriting it is safe.

        {
            const int ksn = ks + STAGES - 1;
            if (ksn < KSTEPS) {
                const size_t gk = (size_t)ksn * TILE_K;
                #pragma unroll
                for (int i = 0; i < 4; i++) {
                    CP_ASYNC16(sA_w + (sw * A_STAGE_FLOATS + i * 4) * 4, gA + gk + i * 4);
                    CP_ASYNC16(sB_w + (sw * B_STAGE_FLOATS + i * 4) * 4, gB + gk + i * 4);
                }
            }
            CP_COMMIT();
            if (++sw == STAGES) sw = 0;
        }

        const uint32_t* Af = reinterpret_cast<const uint32_t*>(As + sr * A_STAGE_FLOATS);
        const uint32_t* Bf = reinterpret_cast<const uint32_t*>(Bs + sr * B_STAGE_FLOATS);
        if (++sr == STAGES) sr = 0;

        #pragma unroll
        for (int kk = 0; kk < TILE_K / 8; kk++) {
            uint32_t b[4][2];
            #pragma unroll
            for (int ni = 0; ni < 4; ni++) {
                const uint32_t* p = Bf + (row_b + ni * 8) * SMA_STRIDE + kk * 8 + col_f;
                b[ni][0] = p[0];
                b[ni][1] = p[4];
            }
            #pragma unroll
            for (int mi = 0; mi < 4; mi++) {
                const uint32_t* p = Af + (row_a + mi * 16) * SMA_STRIDE + kk * 8 + col_f;
                uint32_t a0 = p[0];
                uint32_t a1 = p[8 * SMA_STRIDE];
                uint32_t a2 = p[4];
                uint32_t a3 = p[8 * SMA_STRIDE + 4];
                #pragma unroll
                for (int ni = 0; ni < 4; ni++)
                    mma_tf32(c[mi][ni][0], c[mi][ni][1], c[mi][ni][2], c[mi][ni][3],
                             a0, a1, a2, a3, b[ni][0], b[ni][1]);
            }
        }
    }

    // ---- epilogue: bias + store ----
    float2 bv[4];
    #pragma unroll
    for (int ni = 0; ni < 4; ni++) {
        const int cb = n_base + wn + ni * 8 + (lane & 3) * 2;
        bv[ni].x = __ldg(&bias[cb]);
        bv[ni].y = __ldg(&bias[cb + 1]);
    }
    #pragma unroll
    for (int mi = 0; mi < 4; mi++) {
        const int r0 = m_base + wm + mi * 16 + (lane >> 2);
        #pragma unroll
        for (int ni = 0; ni < 4; ni++) {
            const int cb = n_base + wn + ni * 8 + (lane & 3) * 2;
            float2 v0 = make_float2(c[mi][ni][0] + bv[ni].x, c[mi][ni][1] + bv[ni].y);
            float2 v1 = make_float2(c[mi][ni][2] + bv[ni].x, c[mi][ni][3] + bv[ni].y);
            *reinterpret_cast<float2*>(out + (size_t)r0 * DIM + cb)       = v0;
            *reinterpret_cast<float2*>(out + (size_t)(r0 + 8) * DIM + cb) = v1;
        }
    }
}

// ============================================================================
// Host launcher
// ============================================================================
extern "C" void kernel_launch(void* const* d_in, const int* in_sizes, int n_in,
                              void* d_out, int out_size)
{
    const float* x = nullptr;
    const float* W = nullptr;
    const float* D = nullptr;
    const float* bias = nullptr;
    for (int i = 0; i < n_in; i++) {
        if (in_sizes[i] == DIM * DIM)              x = (const float*)d_in[i];
        else if (in_sizes[i] == KBLK * KBLK * BS)  W = (const float*)d_in[i];
        else if (!D)                               D = (const float*)d_in[i];
        else                                       bias = (const float*)d_in[i];
    }
    float* out = (float*)d_out;

    float* dA = nullptr;
    float* dB = nullptr;
    cudaGetSymbolAddress((void**)&dA, g_A);
    cudaGetSymbolAddress((void**)&dB, g_B);

    prep_a_kernel<<<(DIM * DIM / 4) / 256, 256>>>(x, D, dA);
    prep_b_kernel<<<(DIM * DIM / 4) / 256, 256>>>(W, dB);

    cudaFuncSetAttribute(gemm_tf32_kernel,
                         cudaFuncAttributeMaxDynamicSharedMemorySize, SMEM_TOTAL);

    const int grid = (DIM / TILE_M) * (DIM / TILE_N);   // 32 * 32 = 1024
    gemm_tf32_kernel<<<grid, 256, SMEM_TOTAL>>>(dA, dB, bias, out);
}

// round 7
// speedup vs baseline: 1.1005x; 1.0109x over previous
#include <cuda_runtime.h>
#include <cstdint>

// ============================================================================
// Problem constants
// ============================================================================
#define DIM     4096
#define BS      128
#define KBLK    32

// GEMM tiling
#define TILE_M  128
#define TILE_N  128
#define TILE_K  32
#define STAGES  3
#define KSTEPS  (DIM / TILE_K)      // 128

#define SMA_STRIDE 36               // floats per row (9 float4s), 144B: conflict-free
#define A_STAGE_FLOATS (TILE_M * SMA_STRIDE)   // 4608
#define B_STAGE_FLOATS (TILE_N * SMA_STRIDE)   // 4608
#define SMEM_TOTAL ((STAGES * (A_STAGE_FLOATS + B_STAGE_FLOATS)) * 4)  // 110592 B

static_assert(2 * SMEM_TOTAL <= 227 * 1024, "want 2 CTAs per SM");

// ============================================================================
// Scratch. Staging buffers hold k-PERMUTED data: within each 32-wide k block,
// original column k (k = 32*blk + r) is stored at position p = (r&3)*8 + (r>>2).
// Then the tf32 fragment values a thread (col_f = lane&3) needs -- original
// columns col_f + 4j, j = 0..7 -- live at contiguous positions col_f*8 + j,
// i.e. exactly two float4s.
// ============================================================================
__device__ __align__(1024) float g_A[(size_t)DIM * DIM];   // x * D, tf32, k-permuted
__device__ __align__(1024) float g_B[(size_t)DIM * DIM];   // circulant M, tf32, k-permuted

// ============================================================================
// Helpers
// ============================================================================
__device__ __forceinline__ float tf32_rn(float v) {
    uint32_t r;
    asm("cvt.rna.tf32.f32 %0, %1;" : "=r"(r) : "f"(v));
    return __uint_as_float(r);
}

__device__ __forceinline__ uint32_t smem_u32(const void* p) {
    uint32_t a;
    asm("{ .reg .u64 t; cvta.to.shared.u64 t, %1; cvt.u32.u64 %0, t; }" : "=r"(a) : "l"(p));
    return a;
}

#define CP_ASYNC16(smem_addr, gptr) \
    asm volatile("cp.async.cg.shared.global [%0], [%1], 16;" \
                 :: "r"(smem_addr), "l"(gptr) : "memory")
#define CP_COMMIT() asm volatile("cp.async.commit_group;" ::: "memory")
#define CP_WAIT(n)  asm volatile("cp.async.wait_group %0;" :: "n"(n) : "memory")

__device__ __forceinline__ void mma_tf32(
    float& c0, float& c1, float& c2, float& c3,
    float a0, float a1, float a2, float a3,
    float b0, float b1)
{
    asm volatile(
        "mma.sync.aligned.m16n8k8.row.col.f32.tf32.tf32.f32 "
        "{%0,%1,%2,%3}, {%4,%5,%6,%7}, {%8,%9}, {%0,%1,%2,%3};"
        : "+f"(c0), "+f"(c1), "+f"(c2), "+f"(c3)
        : "r"(__float_as_uint(a0)), "r"(__float_as_uint(a1)),
          "r"(__float_as_uint(a2)), "r"(__float_as_uint(a3)),
          "r"(__float_as_uint(b0)), "r"(__float_as_uint(b1)));
}

// Decompose output float4 index-within-row (q10 in [0,1024)) into the 4 original
// k columns it gathers: q10 = blk*8 + q; covers permuted positions p=4q..4q+3,
// i.e. col_f = q>>1, j = (q&1)*4 + t  ->  k = blk*32 + col_f + 4*j.
__device__ __forceinline__ int perm_gather_base(int q10) {
    int blk = q10 >> 3;
    int q   = q10 & 7;
    return blk * 32 + (q >> 1) + ((q & 1) << 4);   // k for t=0; t adds 4
}

// ============================================================================
// Prep kernels (write k-permuted staging)
// ============================================================================
// A[m, p(k)] = tf32(x[m, k] * D[k])
__global__ void __launch_bounds__(256) prep_a_kernel(
    const float* __restrict__ x, const float* __restrict__ D, float* __restrict__ A)
{
    int i4  = blockIdx.x * blockDim.x + threadIdx.x;   // output float4 index
    int m   = i4 >> 10;
    int q10 = i4 & 1023;
    int k0  = perm_gather_base(q10);
    const float* xr = x + (size_t)m * DIM;
    float4 v;
    v.x = tf32_rn(__ldg(&xr[k0     ]) * __ldg(&D[k0     ]));
    v.y = tf32_rn(__ldg(&xr[k0 +  4]) * __ldg(&D[k0 +  4]));
    v.z = tf32_rn(__ldg(&xr[k0 +  8]) * __ldg(&D[k0 +  8]));
    v.w = tf32_rn(__ldg(&xr[k0 + 12]) * __ldg(&D[k0 + 12]));
    reinterpret_cast<float4*>(A)[i4] = v;
}

// Bm[o, p(k)] = tf32(W[o>>7, k>>7, (k - o) & 127])
__global__ void __launch_bounds__(256) prep_b_kernel(
    const float* __restrict__ W, float* __restrict__ Bm)
{
    int i4  = blockIdx.x * blockDim.x + threadIdx.x;
    int o   = i4 >> 10;
    int q10 = i4 & 1023;
    int k0  = perm_gather_base(q10);
    int i   = o >> 7;
    int t_o = o & 127;
    float4 v;
    #pragma unroll
    for (int t = 0; t < 4; t++) {
        int k = k0 + 4 * t;
        int j = k >> 7;
        int u = k & 127;
        float w = __ldg(&W[((size_t)((i << 5) + j) << 7) + ((u - t_o) & 127)]);
        (&v.x)[t] = tf32_rn(w);
    }
    reinterpret_cast<float4*>(Bm)[i4] = v;
}

// ============================================================================
// TF32 GEMM: out[4096,4096] = A @ Bm^T + bias
// 128x128x32 CTA tile, 256 threads, 8 warps (2m x 4n, warp tile 64x32),
// mma.sync.m16n8k8.tf32, 3-stage cp.async pipeline, 2 CTAs/SM,
// one __syncthreads per k-step, 128-bit fragment loads via k-permuted layout.
// ============================================================================
__global__ void __launch_bounds__(256, 2) gemm_tf32_kernel(
    const float* __restrict__ A, const float* __restrict__ Bm,
    const float* __restrict__ bias, float* __restrict__ out)
{
    extern __shared__ __align__(128) float smem[];
    float* As = smem;
    float* Bs = smem + STAGES * A_STAGE_FLOATS;

    const int tid  = threadIdx.x;
    const int lane = tid & 31;
    const int wid  = tid >> 5;
    const int warp_m = wid & 1;       // 0..1
    const int warp_n = wid >> 1;      // 0..3
    const int wm = warp_m * 64;
    const int wn = warp_n * 32;

    // m fastest in grid -> a wave shares B panels in L2
    const int m_t = blockIdx.x & 31;
    const int n_t = blockIdx.x >> 5;
    const int m_base = m_t * TILE_M;
    const int n_base = n_t * TILE_N;

    // ---- cp.async mapping: thread t loads 4 float4s of one row half ----
    const int ld_row  = tid >> 1;           // 0..127
    const int ld_half = (tid & 1) * 4;      // float4 slot base 0 or 4
    const float* gA = A  + (size_t)(m_base + ld_row) * DIM + ld_half * 4;
    const float* gB = Bm + (size_t)(n_base + ld_row) * DIM + ld_half * 4;
    const uint32_t sA_w = smem_u32(As) + (ld_row * SMA_STRIDE + ld_half * 4) * 4;
    const uint32_t sB_w = smem_u32(Bs) + (ld_row * SMA_STRIDE + ld_half * 4) * 4;

    // ---- fragment read bases (float4 granularity; 9 float4s per row) ----
    const int row_a = wm + (lane >> 2);
    const int row_b = wn + (lane >> 2);
    const int f4c   = (lane & 3) * 2;       // float4 col base for this thread

    float c[4][4][4];
    #pragma unroll
    for (int mi = 0; mi < 4; mi++)
        #pragma unroll
        for (int ni = 0; ni < 4; ni++)
            #pragma unroll
            for (int q = 0; q < 4; q++) c[mi][ni][q] = 0.0f;

    // ---- prologue: fill STAGES-1 stages ----
    #pragma unroll
    for (int s = 0; s < STAGES - 1; s++) {
        const size_t gk = (size_t)s * TILE_K;
        #pragma unroll
        for (int i = 0; i < 4; i++) {
            CP_ASYNC16(sA_w + (s * A_STAGE_FLOATS + i * 4) * 4, gA + gk + i * 4);
            CP_ASYNC16(sB_w + (s * B_STAGE_FLOATS + i * 4) * 4, gB + gk + i * 4);
        }
        CP_COMMIT();
    }

    // ---- mainloop: ONE barrier per k-step ----
    int sw = STAGES - 1;    // stage to write next
    int sr = 0;             // stage to read
    for (int ks = 0; ks < KSTEPS; ks++) {
        CP_WAIT(STAGES - 2);
        __syncthreads();

        {
            const int ksn = ks + STAGES - 1;
            if (ksn < KSTEPS) {
                const size_t gk = (size_t)ksn * TILE_K;
                #pragma unroll
                for (int i = 0; i < 4; i++) {
                    CP_ASYNC16(sA_w + (sw * A_STAGE_FLOATS + i * 4) * 4, gA + gk + i * 4);
                    CP_ASYNC16(sB_w + (sw * B_STAGE_FLOATS + i * 4) * 4, gB + gk + i * 4);
                }
            }
            CP_COMMIT();
            if (++sw == STAGES) sw = 0;
        }

        const float4* Af4 = reinterpret_cast<const float4*>(As + sr * A_STAGE_FLOATS);
        const float4* Bf4 = reinterpret_cast<const float4*>(Bs + sr * B_STAGE_FLOATS);
        if (++sr == STAGES) sr = 0;

        // Two halves: h=0 serves kk=0,1 (j 0..3); h=1 serves kk=2,3 (j 4..7).
        #pragma unroll
        for (int h = 0; h < 2; h++) {
            float4 bfr[4];
            #pragma unroll
            for (int ni = 0; ni < 4; ni++)
                bfr[ni] = Bf4[(row_b + ni * 8) * 9 + f4c + h];
            float4 alo[4], ahi[4];
            #pragma unroll
            for (int mi = 0; mi < 4; mi++) {
                alo[mi] = Af4[(row_a + mi * 16)     * 9 + f4c + h];
                ahi[mi] = Af4[(row_a + mi * 16 + 8) * 9 + f4c + h];
            }
            #pragma unroll
            for (int mi = 0; mi < 4; mi++) {
                #pragma unroll
                for (int ni = 0; ni < 4; ni++) {
                    // kk = 2h:   a0=lo.x a1=hi.x a2=lo.y a3=hi.y  b=(x,y)
                    mma_tf32(c[mi][ni][0], c[mi][ni][1], c[mi][ni][2], c[mi][ni][3],
                             alo[mi].x, ahi[mi].x, alo[mi].y, ahi[mi].y,
                             bfr[ni].x, bfr[ni].y);
                    // kk = 2h+1: a0=lo.z a1=hi.z a2=lo.w a3=hi.w  b=(z,w)
                    mma_tf32(c[mi][ni][0], c[mi][ni][1], c[mi][ni][2], c[mi][ni][3],
                             alo[mi].z, ahi[mi].z, alo[mi].w, ahi[mi].w,
                             bfr[ni].z, bfr[ni].w);
                }
            }
        }
    }

    // ---- epilogue: bias + store ----
    float2 bv[4];
    #pragma unroll
    for (int ni = 0; ni < 4; ni++) {
        const int cb = n_base + wn + ni * 8 + (lane & 3) * 2;
        bv[ni].x = __ldg(&bias[cb]);
        bv[ni].y = __ldg(&bias[cb + 1]);
    }
    #pragma unroll
    for (int mi = 0; mi < 4; mi++) {
        const int r0 = m_base + wm + mi * 16 + (lane >> 2);
        #pragma unroll
        for (int ni = 0; ni < 4; ni++) {
            const int cb = n_base + wn + ni * 8 + (lane & 3) * 2;
            float2 v0 = make_float2(c[mi][ni][0] + bv[ni].x, c[mi][ni][1] + bv[ni].y);
            float2 v1 = make_float2(c[mi][ni][2] + bv[ni].x, c[mi][ni][3] + bv[ni].y);
            *reinterpret_cast<float2*>(out + (size_t)r0 * DIM + cb)       = v0;
            *reinterpret_cast<float2*>(out + (size_t)(r0 + 8) * DIM + cb) = v1;
        }
    }
}

// ============================================================================
// Host launcher
// ============================================================================
extern "C" void kernel_launch(void* const* d_in, const int* in_sizes, int n_in,
                              void* d_out, int out_size)
{
    const float* x = nullptr;
    const float* W = nullptr;
    const float* D = nullptr;
    const float* bias = nullptr;
    for (int i = 0; i < n_in; i++) {
        if (in_sizes[i] == DIM * DIM)              x = (const float*)d_in[i];
        else if (in_sizes[i] == KBLK * KBLK * BS)  W = (const float*)d_in[i];
        else if (!D)                               D = (const float*)d_in[i];
        else                                       bias = (const float*)d_in[i];
    }
    float* out = (float*)d_out;

    float* dA = nullptr;
    float* dB = nullptr;
    cudaGetSymbolAddress((void**)&dA, g_A);
    cudaGetSymbolAddress((void**)&dB, g_B);

    prep_a_kernel<<<(DIM * DIM / 4) / 256, 256>>>(x, D, dA);
    prep_b_kernel<<<(DIM * DIM / 4) / 256, 256>>>(W, dB);

    cudaFuncSetAttribute(gemm_tf32_kernel,
                         cudaFuncAttributeMaxDynamicSharedMemorySize, SMEM_TOTAL);

    const int grid = (DIM / TILE_M) * (DIM / TILE_N);   // 32 * 32 = 1024
    gemm_tf32_kernel<<<grid, 256, SMEM_TOTAL>>>(dA, dB, bias, out);
}

// round 8
// speedup vs baseline: 1.9132x; 1.7386x over previous
#include <cuda_runtime.h>
#include <cstdint>

// ============================================================================
// Problem constants
// ============================================================================
#define DIM    4096
#define BS     128          // circulant block size
#define KBLK   32           // blocks per dim
#define FB     65           // rfft bins (0..64)
#define NROWS  131072       // 4096 batch * 32 blocks

// ============================================================================
// FFT-domain pipeline, all fp32:
//   Stage1: Xf = (x*D) @ F1          [131072x128]@[128x130]
//   Stage2: per-bin Of = X2 @ W2^T   65 x ([4096x64]@[64x64])
//   Stage3: out = Of @ F3 + bias     [131072x130]@[130x128]
// F1[u][2f+c]: c=0 -> cos(2pi f u/128), c=1 -> -sin(2pi f u/128)   (true fft)
// W2 encodes complex product with conj(fft(W)) = (WR', WI'), WI' = +sum W sin
// F3[(2f+c)][t]: a_f/128 * (c=0: cos(2pi f t/128), c=1: -sin(...)), a={1,2,..,2,1}
// ============================================================================

// Scratch (device globals; no runtime allocation)
__device__ float g_Xf[(size_t)FB * 4096 * 64];     // [f][b][2j+c]  68.2 MB
__device__ float g_Of[(size_t)NROWS * 130];        // [(b*32+i)][2f+c]  68.2 MB
__device__ float g_W2[FB * 64 * 64];               // [f][n][k]
__device__ float g_F1[128 * 130];                  // [u][2f+c]
__device__ float g_F3[130 * 128];                  // [2f+c][t]

// ============================================================================
// Builder kernels
// ============================================================================
__global__ void __launch_bounds__(256) k_build_F()
{
    int idx = blockIdx.x * blockDim.x + threadIdx.x;
    if (idx < 128 * 130) {
        // F1
        int u   = idx / 130;
        int col = idx - u * 130;
        int f   = col >> 1;
        int m   = (f * u) & 127;
        float th = (float)m * (1.0f / 64.0f);
        g_F1[idx] = (col & 1) ? -sinpif(th) : cospif(th);
    } else if (idx < 2 * 128 * 130) {
        // F3
        int j = idx - 128 * 130;
        int r = j >> 7;          // 0..129 = 2f+c
        int t = j & 127;
        int f = r >> 1;
        int m = (f * t) & 127;
        float th = (float)m * (1.0f / 64.0f);
        float a  = (f == 0 || f == 64) ? 1.0f : 2.0f;
        float v  = (r & 1) ? -sinpif(th) : cospif(th);
        g_F3[j] = v * a * (1.0f / 128.0f);
    }
}

// W2 per bin: WR' = sum_u W cos, WI' = +sum_u W sin  (conj of fft)
// Or = XR*WR' - XI*WI' ; Oi = XR*WI' + XI*WR'
__global__ void __launch_bounds__(256) k_build_W2(const float* __restrict__ W)
{
    int g = blockIdx.x * blockDim.x + threadIdx.x;   // 65*1024 threads
    if (g >= FB * 1024) return;
    int f = g >> 10;
    int r = g & 1023;            // r = i*32 + j
    int i = r >> 5;
    int j = r & 31;
    const float* wrow = W + (size_t)r * 128;
    float wr = 0.0f, wi = 0.0f;
    #pragma unroll 4
    for (int u = 0; u < 128; u++) {
        float wv = wrow[u];
        wr += wv * g_F1[u * 130 + 2 * f];          // cos
        wi -= wv * g_F1[u * 130 + 2 * f + 1];      // -(-sin) = +sin
    }
    float* W2f = g_W2 + (size_t)f * 4096;
    int n0 = 2 * i, n1 = 2 * i + 1;
    int k0 = 2 * j, k1 = 2 * j + 1;
    W2f[n0 * 64 + k0] =  wr;
    W2f[n0 * 64 + k1] = -wi;
    W2f[n1 * 64 + k0] =  wi;
    W2f[n1 * 64 + k1] =  wr;
}

// ============================================================================
// Stage 1: Xf = (x*D) @ F1.  CTA: 128 rows x 144 cols(130 used), K=128.
// 288 threads (16x18), thread tile 8x8. smem: A^T [128][132] + B [128][148].
// ============================================================================
#define S1_AT_STRIDE 132
#define S1_B_STRIDE  148
#define S1_SMEM ((128 * S1_AT_STRIDE + 128 * S1_B_STRIDE) * 4)   // 143360 B

__global__ void __launch_bounds__(288, 1) k_stage1(
    const float* __restrict__ x, const float* __restrict__ D)
{
    extern __shared__ __align__(16) float smem[];
    float* At = smem;                         // [u][row]
    float* Bs = smem + 128 * S1_AT_STRIDE;    // [u][col]

    const int tid = threadIdx.x;
    const int r0  = blockIdx.x * 128;

    // Stage A (transposed), with x*D applied
    for (int i = tid; i < 128 * 128; i += 288) {
        int r = i >> 7;
        int u = i & 127;
        float v = x[(size_t)(r0 + r) * 128 + u] * D[((r & 31) << 7) + u];
        At[u * S1_AT_STRIDE + r] = v;
    }
    // Stage B (zero-pad cols 130..143)
    for (int i = tid; i < 128 * 144; i += 288) {
        int u   = i / 144;
        int col = i - u * 144;
        Bs[u * S1_B_STRIDE + col] = (col < 130) ? g_F1[u * 130 + col] : 0.0f;
    }
    __syncthreads();

    const int tr = tid / 18;       // 0..15
    const int tc = tid - tr * 18;  // 0..17
    const int R0 = tr * 8;
    const int C0 = tc * 8;

    float acc[8][8];
    #pragma unroll
    for (int a = 0; a < 8; a++)
        #pragma unroll
        for (int b = 0; b < 8; b++) acc[a][b] = 0.0f;

    for (int u = 0; u < 128; u++) {
        float4 a0 = *reinterpret_cast<const float4*>(&At[u * S1_AT_STRIDE + R0]);
        float4 a1 = *reinterpret_cast<const float4*>(&At[u * S1_AT_STRIDE + R0 + 4]);
        float4 b0 = *reinterpret_cast<const float4*>(&Bs[u * S1_B_STRIDE + C0]);
        float4 b1 = *reinterpret_cast<const float4*>(&Bs[u * S1_B_STRIDE + C0 + 4]);
        float av[8] = {a0.x, a0.y, a0.z, a0.w, a1.x, a1.y, a1.z, a1.w};
        float bv[8] = {b0.x, b0.y, b0.z, b0.w, b1.x, b1.y, b1.z, b1.w};
        #pragma unroll
        for (int rr = 0; rr < 8; rr++)
            #pragma unroll
            for (int cc = 0; cc < 8; cc++)
                acc[rr][cc] = fmaf(av[rr], bv[cc], acc[rr][cc]);
    }

    // Scatter store into g_Xf[f][b][2j+c]
    #pragma unroll
    for (int rr = 0; rr < 8; rr++) {
        int rg = r0 + R0 + rr;
        int b  = rg >> 5;
        int j2 = (rg & 31) << 1;
        #pragma unroll
        for (int cc = 0; cc < 8; cc++) {
            int col = C0 + cc;
            if (col < 130) {
                int f = col >> 1;
                int c = col & 1;
                g_Xf[((size_t)f * 4096 + b) * 64 + j2 + c] = acc[rr][cc];
            }
        }
    }
}

// ============================================================================
// Stage 2: per bin f: Of_chunk = X2[128x64] @ W2[64x64]^T.
// Grid 65*32; 256 threads (16 rows x 16 cols), thread tile 8x4.
// smem: X2^T [64][132] + W2^T [64][68].
// ============================================================================
#define S2_XT_STRIDE 132
#define S2_W_STRIDE  68
#define S2_SMEM ((64 * S2_XT_STRIDE + 64 * S2_W_STRIDE) * 4)   // 51200 B

__global__ void __launch_bounds__(256) k_stage2()
{
    extern __shared__ __align__(16) float smem[];
    float* Xt  = smem;                        // [k][row]
    float* W2s = smem + 64 * S2_XT_STRIDE;    // [k][n]

    const int tid = threadIdx.x;
    const int f   = blockIdx.x >> 5;          // /32
    const int b0  = (blockIdx.x & 31) * 128;

    const float* Xf_bin = g_Xf + (size_t)f * 4096 * 64;
    const float* W2f    = g_W2 + (size_t)f * 4096;

    for (int i = tid; i < 128 * 64; i += 256) {
        int row = i >> 6;
        int k   = i & 63;
        Xt[k * S2_XT_STRIDE + row] = Xf_bin[(size_t)(b0 + row) * 64 + k];
    }
    for (int i = tid; i < 4096; i += 256) {
        int n = i >> 6;
        int k = i & 63;
        W2s[k * S2_W_STRIDE + n] = W2f[n * 64 + k];
    }
    __syncthreads();

    const int tr = tid & 15;
    const int tc = tid >> 4;
    const int R0 = tr * 8;
    const int C0 = tc * 4;

    float acc[8][4];
    #pragma unroll
    for (int a = 0; a < 8; a++)
        #pragma unroll
        for (int b = 0; b < 4; b++) acc[a][b] = 0.0f;

    for (int k = 0; k < 64; k++) {
        float4 a0 = *reinterpret_cast<const float4*>(&Xt[k * S2_XT_STRIDE + R0]);
        float4 a1 = *reinterpret_cast<const float4*>(&Xt[k * S2_XT_STRIDE + R0 + 4]);
        float4 bv = *reinterpret_cast<const float4*>(&W2s[k * S2_W_STRIDE + C0]);
        float av[8] = {a0.x, a0.y, a0.z, a0.w, a1.x, a1.y, a1.z, a1.w};
        float bb[4] = {bv.x, bv.y, bv.z, bv.w};
        #pragma unroll
        for (int rr = 0; rr < 8; rr++)
            #pragma unroll
            for (int cc = 0; cc < 4; cc++)
                acc[rr][cc] = fmaf(av[rr], bb[cc], acc[rr][cc]);
    }

    // Scatter store into g_Of[(b*32+i)][2f+c]
    #pragma unroll
    for (int rr = 0; rr < 8; rr++) {
        int brow = b0 + R0 + rr;
        #pragma unroll
        for (int cc = 0; cc < 4; cc++) {
            int n  = C0 + cc;
            int io = n >> 1;
            int c  = n & 1;
            g_Of[((size_t)brow * 32 + io) * 130 + 2 * f + c] = acc[rr][cc];
        }
    }
}

// ============================================================================
// Stage 3: out = Of @ F3 + bias.  CTA: 128 rows x 128 cols, K=130.
// 256 threads (16x16), thread tile 8x8. smem: A^T [130][132] + B [130][132].
// ============================================================================
#define S3_STRIDE 132
#define S3_SMEM ((130 * S3_STRIDE + 130 * S3_STRIDE) * 4)   // 137280 B

__global__ void __launch_bounds__(256, 1) k_stage3(
    const float* __restrict__ bias, float* __restrict__ out)
{
    extern __shared__ __align__(16) float smem[];
    float* At = smem;                       // [k][row]
    float* Bs = smem + 130 * S3_STRIDE;     // [k][t]

    const int tid = threadIdx.x;
    const int r0  = blockIdx.x * 128;

    for (int i = tid; i < 128 * 130; i += 256) {
        int r = i / 130;
        int k = i - r * 130;
        At[k * S3_STRIDE + r] = g_Of[(size_t)(r0 + r) * 130 + k];
    }
    for (int i = tid; i < 130 * 128; i += 256) {
        int k = i >> 7;
        int t = i & 127;
        Bs[k * S3_STRIDE + t] = g_F3[i];
    }
    __syncthreads();

    const int tr = tid >> 4;
    const int tc = tid & 15;
    const int R0 = tr * 8;
    const int C0 = tc * 8;

    float acc[8][8];
    #pragma unroll
    for (int a = 0; a < 8; a++)
        #pragma unroll
        for (int b = 0; b < 8; b++) acc[a][b] = 0.0f;

    for (int k = 0; k < 130; k++) {
        float4 a0 = *reinterpret_cast<const float4*>(&At[k * S3_STRIDE + R0]);
        float4 a1 = *reinterpret_cast<const float4*>(&At[k * S3_STRIDE + R0 + 4]);
        float4 b0 = *reinterpret_cast<const float4*>(&Bs[k * S3_STRIDE + C0]);
        float4 b1 = *reinterpret_cast<const float4*>(&Bs[k * S3_STRIDE + C0 + 4]);
        float av[8] = {a0.x, a0.y, a0.z, a0.w, a1.x, a1.y, a1.z, a1.w};
        float bv[8] = {b0.x, b0.y, b0.z, b0.w, b1.x, b1.y, b1.z, b1.w};
        #pragma unroll
        for (int rr = 0; rr < 8; rr++)
            #pragma unroll
            for (int cc = 0; cc < 8; cc++)
                acc[rr][cc] = fmaf(av[rr], bv[cc], acc[rr][cc]);
    }

    // Coalesced store with bias
    #pragma unroll
    for (int rr = 0; rr < 8; rr++) {
        int rg = r0 + R0 + rr;
        int ii = rg & 31;                       // i within batch row
        float* orow = out + (size_t)rg * 128;   // out[b][i*128 + t]
        const float* brow = bias + (ii << 7);
        float4 v0, v1;
        v0.x = acc[rr][0] + brow[C0 + 0];
        v0.y = acc[rr][1] + brow[C0 + 1];
        v0.z = acc[rr][2] + brow[C0 + 2];
        v0.w = acc[rr][3] + brow[C0 + 3];
        v1.x = acc[rr][4] + brow[C0 + 4];
        v1.y = acc[rr][5] + brow[C0 + 5];
        v1.z = acc[rr][6] + brow[C0 + 6];
        v1.w = acc[rr][7] + brow[C0 + 7];
        *reinterpret_cast<float4*>(orow + C0)     = v0;
        *reinterpret_cast<float4*>(orow + C0 + 4) = v1;
    }
}

// ============================================================================
// Host launcher
// ============================================================================
extern "C" void kernel_launch(void* const* d_in, const int* in_sizes, int n_in,
                              void* d_out, int out_size)
{
    const float* x = nullptr;
    const float* W = nullptr;
    const float* D = nullptr;
    const float* bias = nullptr;
    for (int i = 0; i < n_in; i++) {
        if (in_sizes[i] == DIM * DIM)              x = (const float*)d_in[i];
        else if (in_sizes[i] == KBLK * KBLK * BS)  W = (const float*)d_in[i];
        else if (!D)                               D = (const float*)d_in[i];
        else                                       bias = (const float*)d_in[i];
    }
    float* out = (float*)d_out;

    static bool attr_done = false;
    if (!attr_done) {
        cudaFuncSetAttribute(k_stage1, cudaFuncAttributeMaxDynamicSharedMemorySize, S1_SMEM);
        cudaFuncSetAttribute(k_stage2, cudaFuncAttributeMaxDynamicSharedMemorySize, S2_SMEM);
        cudaFuncSetAttribute(k_stage3, cudaFuncAttributeMaxDynamicSharedMemorySize, S3_SMEM);
        attr_done = true;
    }

    // Builders (cheap; rebuilt every call for determinism)
    k_build_F<<<(2 * 128 * 130 + 255) / 256, 256>>>();
    k_build_W2<<<(FB * 1024 + 255) / 256, 256>>>(W);

    // Pipeline
    k_stage1<<<NROWS / 128, 288, S1_SMEM>>>(x, D);
    k_stage2<<<FB * 32, 256, S2_SMEM>>>();
    k_stage3<<<NROWS / 128, 256, S3_SMEM>>>(bias, out);
}

// round 9
// speedup vs baseline: 4.4151x; 2.3077x over previous
#include <cuda_runtime.h>
#include <cstdint>

// ============================================================================
// Problem constants
// ============================================================================
#define DIM    4096
#define KBLK   32
#define FB     65           // rfft bins 0..64
#define NROWS  131072       // 4096 batch * 32 blocks

// ============================================================================
// FFT-domain pipeline, tf32 tensor cores:
//   Stage1: Xf = (x*D) @ F1p         [131072x128]@[128x160] (130 used)
//   Stage2: per-bin Of = X2 @ W2^T   65 x ([4096x64]@[64x64])
//   Stage3: out = Of @ F3p^T + bias  [131072x136]@[136x128] (130 used)
// Layouts (chosen for coalescing):
//   g_Xf[f][b][2j+c]   : stage2 loads coalesced (64-float rows per b)
//   g_Of[f][brow][c]   : stage2 stores coalesced (32B runs), stage3 loads ok
// ============================================================================
__device__ float g_Xf[(size_t)FB * 4096 * 64];     // 68.2 MB
__device__ float g_Of[(size_t)FB * NROWS * 2];     // 68.2 MB
__device__ float g_W2[FB * 64 * 64];               // [f][n=2i+c][k=2j+c'] tf32
__device__ float g_F1p[160 * 128];                 // [n=2f+c][u] tf32, 0 for n>=130
__device__ float g_F3p[128 * 136];                 // [t][k=2f+c] tf32, 0 for k>=130

// ============================================================================
// Helpers
// ============================================================================
__device__ __forceinline__ float tf32_rn(float v) {
    uint32_t r;
    asm("cvt.rna.tf32.f32 %0, %1;" : "=r"(r) : "f"(v));
    return __uint_as_float(r);
}

__device__ __forceinline__ void mma_tf32(
    float& c0, float& c1, float& c2, float& c3,
    float a0, float a1, float a2, float a3,
    float b0, float b1)
{
    asm volatile(
        "mma.sync.aligned.m16n8k8.row.col.f32.tf32.tf32.f32 "
        "{%0,%1,%2,%3}, {%4,%5,%6,%7}, {%8,%9}, {%0,%1,%2,%3};"
        : "+f"(c0), "+f"(c1), "+f"(c2), "+f"(c3)
        : "r"(__float_as_uint(a0)), "r"(__float_as_uint(a1)),
          "r"(__float_as_uint(a2)), "r"(__float_as_uint(a3)),
          "r"(__float_as_uint(b0)), "r"(__float_as_uint(b1)));
}

// ============================================================================
// Builders
// ============================================================================
__global__ void __launch_bounds__(256) k_build_F()
{
    int idx = blockIdx.x * blockDim.x + threadIdx.x;
    if (idx < 160 * 128) {
        // F1p[n][u]: n=2f+c -> c=0: cos(2pi f u/128), c=1: -sin(...); 0 for n>=130
        int n = idx >> 7;
        int u = idx & 127;
        float v = 0.0f;
        if (n < 130) {
            int f = n >> 1;
            int m = (f * u) & 127;
            float th = (float)m * (1.0f / 64.0f);
            v = (n & 1) ? -sinpif(th) : cospif(th);
        }
        g_F1p[idx] = tf32_rn(v);
    } else if (idx < 160 * 128 + 128 * 136) {
        // F3p[t][k]: k=2f+c -> a_f/128 * (c=0: cos(2pi f t/128), c=1: -sin); 0 k>=130
        int j = idx - 160 * 128;
        int t = j / 136;
        int k = j - t * 136;
        float v = 0.0f;
        if (k < 130) {
            int f = k >> 1;
            int m = (f * t) & 127;
            float th = (float)m * (1.0f / 64.0f);
            float a  = (f == 0 || f == 64) ? 1.0f : 2.0f;
            v = ((k & 1) ? -sinpif(th) : cospif(th)) * a * (1.0f / 128.0f);
        }
        g_F3p[j] = tf32_rn(v);
    }
}

// One warp per (f, r) task, lanes span u (coalesced W reads), shfl reduce.
// WR' = sum_u W cos, WI' = +sum_u W sin (conj of fft).
__global__ void __launch_bounds__(256) k_build_W2(const float* __restrict__ W)
{
    int wg   = (blockIdx.x * 256 + threadIdx.x) >> 5;
    int lane = threadIdx.x & 31;
    if (wg >= FB * 1024) return;
    int f = wg >> 10;
    int r = wg & 1023;           // r = i*32 + j
    const float* wrow = W + (size_t)r * 128;
    const float* crow = g_F1p + (2 * f) * 128;
    const float* srow = g_F1p + (2 * f + 1) * 128;   // holds -sin
    float wr = 0.0f, wi = 0.0f;
    #pragma unroll
    for (int t = 0; t < 4; t++) {
        float wv = wrow[lane + 32 * t];
        wr += wv * crow[lane + 32 * t];
        wi -= wv * srow[lane + 32 * t];              // -(-sin) = +sin
    }
    #pragma unroll
    for (int off = 16; off; off >>= 1) {
        wr += __shfl_xor_sync(0xFFFFFFFFu, wr, off);
        wi += __shfl_xor_sync(0xFFFFFFFFu, wi, off);
    }
    if (lane == 0) {
        int i = r >> 5, j = r & 31;
        float* W2f = g_W2 + (size_t)f * 4096;
        int n0 = 2 * i, n1 = 2 * i + 1, k0 = 2 * j, k1 = 2 * j + 1;
        W2f[n0 * 64 + k0] = tf32_rn( wr);
        W2f[n0 * 64 + k1] = tf32_rn(-wi);
        W2f[n1 * 64 + k0] = tf32_rn( wi);
        W2f[n1 * 64 + k1] = tf32_rn( wr);
    }
}

// ============================================================================
// Stage 1: Xf = (x*D) @ F1p^T.  CTA 128x160, K=128 single pass. 8 warps 2m x 4n,
// warp tile 64x40. smem: A[128][132] row-major, B[160][132] row-major [n][k].
// ============================================================================
#define S1_AST 132
#define S1_BST 132
#define S1_SMEM ((128 * S1_AST + 160 * S1_BST) * 4)   // 152064 B

__global__ void __launch_bounds__(256, 1) k_stage1(
    const float* __restrict__ x, const float* __restrict__ D)
{
    extern __shared__ __align__(16) float smem[];
    float* As = smem;
    float* Bs = smem + 128 * S1_AST;

    const int tid = threadIdx.x;
    const int r0  = blockIdx.x * 128;

    // A fill: tf32(x * D), float4 granules, coalesced
    for (int i4 = tid; i4 < 128 * 32; i4 += 256) {
        int r  = i4 >> 5;
        int u4 = (i4 & 31) << 2;
        float4 xv = *reinterpret_cast<const float4*>(&x[(size_t)(r0 + r) * 128 + u4]);
        float4 dv = *reinterpret_cast<const float4*>(&D[(((r0 + r) & 31) << 7) + u4]);
        float4 v;
        v.x = tf32_rn(xv.x * dv.x);
        v.y = tf32_rn(xv.y * dv.y);
        v.z = tf32_rn(xv.z * dv.z);
        v.w = tf32_rn(xv.w * dv.w);
        *reinterpret_cast<float4*>(&As[r * S1_AST + u4]) = v;
    }
    // B fill (pre-rounded, pre-padded)
    for (int i4 = tid; i4 < 160 * 32; i4 += 256) {
        int n  = i4 >> 5;
        int k4 = (i4 & 31) << 2;
        *reinterpret_cast<float4*>(&Bs[n * S1_BST + k4]) =
            *reinterpret_cast<const float4*>(&g_F1p[n * 128 + k4]);
    }
    __syncthreads();

    const int lane = tid & 31;
    const int wid  = tid >> 5;
    const int wm = (wid & 1) * 64;
    const int wn = (wid >> 1) * 40;
    const int row_a = wm + (lane >> 2);
    const int row_b = wn + (lane >> 2);
    const int col_f = lane & 3;

    float c[4][5][4];
    #pragma unroll
    for (int mi = 0; mi < 4; mi++)
        #pragma unroll
        for (int ni = 0; ni < 5; ni++)
            #pragma unroll
            for (int q = 0; q < 4; q++) c[mi][ni][q] = 0.0f;

    #pragma unroll
    for (int kk = 0; kk < 16; kk++) {
        float b[5][2];
        #pragma unroll
        for (int ni = 0; ni < 5; ni++) {
            const float* p = &Bs[(row_b + ni * 8) * S1_BST + kk * 8 + col_f];
            b[ni][0] = p[0];
            b[ni][1] = p[4];
        }
        #pragma unroll
        for (int mi = 0; mi < 4; mi++) {
            const float* p = &As[(row_a + mi * 16) * S1_AST + kk * 8 + col_f];
            float a0 = p[0], a1 = p[8 * S1_AST], a2 = p[4], a3 = p[8 * S1_AST + 4];
            #pragma unroll
            for (int ni = 0; ni < 5; ni++)
                mma_tf32(c[mi][ni][0], c[mi][ni][1], c[mi][ni][2], c[mi][ni][3],
                         a0, a1, a2, a3, b[ni][0], b[ni][1]);
        }
    }

    // Scatter store: (row r, col n=2f+c) -> g_Xf[f][r>>5][(r&31)*2 + c]
    #pragma unroll
    for (int mi = 0; mi < 4; mi++) {
        int rg1 = r0 + wm + mi * 16 + (lane >> 2);
        int rg2 = rg1 + 8;
        #pragma unroll
        for (int ni = 0; ni < 5; ni++) {
            int n0 = wn + ni * 8 + 2 * (lane & 3);
            if (n0 < 130) {
                size_t base = (size_t)(n0 >> 1) * 262144;
                *reinterpret_cast<float2*>(
                    &g_Xf[base + (rg1 >> 5) * 64 + ((rg1 & 31) << 1)]) =
                    make_float2(c[mi][ni][0], c[mi][ni][1]);
                *reinterpret_cast<float2*>(
                    &g_Xf[base + (rg2 >> 5) * 64 + ((rg2 & 31) << 1)]) =
                    make_float2(c[mi][ni][2], c[mi][ni][3]);
            }
        }
    }
}

// ============================================================================
// Stage 2: per bin f: Of = X2[256x64] @ W2[64x64]^T.  8 warps 4m x 2n,
// warp tile 64x32. smem: X[256][68], W2[64][68].
// ============================================================================
#define S2_AST 68
#define S2_BST 68
#define S2_SMEM ((256 * S2_AST + 64 * S2_BST) * 4)   // 87040 B

__global__ void __launch_bounds__(256, 2) k_stage2()
{
    extern __shared__ __align__(16) float smem[];
    float* Xs = smem;
    float* Ws = smem + 256 * S2_AST;

    const int tid = threadIdx.x;
    const int f   = blockIdx.x >> 4;
    const int b0  = (blockIdx.x & 15) * 256;

    const float* Xf_bin = g_Xf + (size_t)f * 262144;
    const float* W2f    = g_W2 + (size_t)f * 4096;

    for (int i4 = tid; i4 < 256 * 16; i4 += 256) {
        int row = i4 >> 4;
        int k4  = (i4 & 15) << 2;
        float4 v = *reinterpret_cast<const float4*>(&Xf_bin[(size_t)(b0 + row) * 64 + k4]);
        v.x = tf32_rn(v.x); v.y = tf32_rn(v.y); v.z = tf32_rn(v.z); v.w = tf32_rn(v.w);
        *reinterpret_cast<float4*>(&Xs[row * S2_AST + k4]) = v;
    }
    for (int i4 = tid; i4 < 64 * 16; i4 += 256) {
        int n  = i4 >> 4;
        int k4 = (i4 & 15) << 2;
        *reinterpret_cast<float4*>(&Ws[n * S2_BST + k4]) =
            *reinterpret_cast<const float4*>(&W2f[n * 64 + k4]);
    }
    __syncthreads();

    const int lane = tid & 31;
    const int wid  = tid >> 5;
    const int wm = (wid & 3) * 64;
    const int wn = (wid >> 2) * 32;
    const int row_a = wm + (lane >> 2);
    const int row_b = wn + (lane >> 2);
    const int col_f = lane & 3;

    float c[4][4][4];
    #pragma unroll
    for (int mi = 0; mi < 4; mi++)
        #pragma unroll
        for (int ni = 0; ni < 4; ni++)
            #pragma unroll
            for (int q = 0; q < 4; q++) c[mi][ni][q] = 0.0f;

    #pragma unroll
    for (int kk = 0; kk < 8; kk++) {
        float b[4][2];
        #pragma unroll
        for (int ni = 0; ni < 4; ni++) {
            const float* p = &Ws[(row_b + ni * 8) * S2_BST + kk * 8 + col_f];
            b[ni][0] = p[0];
            b[ni][1] = p[4];
        }
        #pragma unroll
        for (int mi = 0; mi < 4; mi++) {
            const float* p = &Xs[(row_a + mi * 16) * S2_AST + kk * 8 + col_f];
            float a0 = p[0], a1 = p[8 * S2_AST], a2 = p[4], a3 = p[8 * S2_AST + 4];
            #pragma unroll
            for (int ni = 0; ni < 4; ni++)
                mma_tf32(c[mi][ni][0], c[mi][ni][1], c[mi][ni][2], c[mi][ni][3],
                         a0, a1, a2, a3, b[ni][0], b[ni][1]);
        }
    }

    // Store: (row b, col n=2i+c) -> g_Of[f][b*32+i][c]  (coalesced 32B runs)
    float* Of_f = g_Of + (size_t)f * 262144;
    #pragma unroll
    for (int mi = 0; mi < 4; mi++) {
        int b1 = b0 + wm + mi * 16 + (lane >> 2);
        int b2 = b1 + 8;
        #pragma unroll
        for (int ni = 0; ni < 4; ni++) {
            int n0 = wn + ni * 8 + 2 * (lane & 3);
            int i  = n0 >> 1;
            *reinterpret_cast<float2*>(&Of_f[(size_t)(b1 * 32 + i) * 2]) =
                make_float2(c[mi][ni][0], c[mi][ni][1]);
            *reinterpret_cast<float2*>(&Of_f[(size_t)(b2 * 32 + i) * 2]) =
                make_float2(c[mi][ni][2], c[mi][ni][3]);
        }
    }
}

// ============================================================================
// Stage 3: out = Of @ F3p^T + bias.  CTA 128x128, K=136 (130 used). 8 warps
// 2m x 4n, warp tile 64x32. smem: A[128][140], B[128][140].
// ============================================================================
#define S3_AST 140
#define S3_BST 140
#define S3_SMEM ((128 * S3_AST + 128 * S3_BST) * 4)   // 143360 B

__global__ void __launch_bounds__(256, 1) k_stage3(
    const float* __restrict__ bias, float* __restrict__ out)
{
    extern __shared__ __align__(16) float smem[];
    float* As = smem;
    float* Bs = smem + 128 * S3_AST;

    const int tid = threadIdx.x;
    const int r0  = blockIdx.x * 128;

    // A fill: k = 2f+c from g_Of[f][r0+r][c]; r-consecutive threads -> coalesced
    for (int i = tid; i < 128 * 136; i += 256) {
        int r = i & 127;
        int k = i >> 7;
        float v = 0.0f;
        if (k < 130) {
            int f = k >> 1, cc = k & 1;
            v = tf32_rn(g_Of[(size_t)f * 262144 + (size_t)(r0 + r) * 2 + cc]);
        }
        As[r * S3_AST + k] = v;
    }
    // B fill from pre-built F3p [t][136]
    for (int i4 = tid; i4 < 128 * 34; i4 += 256) {
        int t  = i4 / 34;
        int k4 = (i4 - t * 34) << 2;
        *reinterpret_cast<float4*>(&Bs[t * S3_BST + k4]) =
            *reinterpret_cast<const float4*>(&g_F3p[t * 136 + k4]);
    }
    __syncthreads();

    const int lane = tid & 31;
    const int wid  = tid >> 5;
    const int wm = (wid & 1) * 64;
    const int wn = (wid >> 1) * 32;
    const int row_a = wm + (lane >> 2);
    const int row_b = wn + (lane >> 2);
    const int col_f = lane & 3;

    float c[4][4][4];
    #pragma unroll
    for (int mi = 0; mi < 4; mi++)
        #pragma unroll
        for (int ni = 0; ni < 4; ni++)
            #pragma unroll
            for (int q = 0; q < 4; q++) c[mi][ni][q] = 0.0f;

    #pragma unroll
    for (int kk = 0; kk < 17; kk++) {
        float b[4][2];
        #pragma unroll
        for (int ni = 0; ni < 4; ni++) {
            const float* p = &Bs[(row_b + ni * 8) * S3_BST + kk * 8 + col_f];
            b[ni][0] = p[0];
            b[ni][1] = p[4];
        }
        #pragma unroll
        for (int mi = 0; mi < 4; mi++) {
            const float* p = &As[(row_a + mi * 16) * S3_AST + kk * 8 + col_f];
            float a0 = p[0], a1 = p[8 * S3_AST], a2 = p[4], a3 = p[8 * S3_AST + 4];
            #pragma unroll
            for (int ni = 0; ni < 4; ni++)
                mma_tf32(c[mi][ni][0], c[mi][ni][1], c[mi][ni][2], c[mi][ni][3],
                         a0, a1, a2, a3, b[ni][0], b[ni][1]);
        }
    }

    // Store with bias: row rg = b*32+i, col t -> out[rg*128 + t]
    #pragma unroll
    for (int mi = 0; mi < 4; mi++) {
        int rg1 = r0 + wm + mi * 16 + (lane >> 2);
        int rg2 = rg1 + 8;
        #pragma unroll
        for (int ni = 0; ni < 4; ni++) {
            int cb = wn + ni * 8 + 2 * (lane & 3);
            float2 bv1 = __ldg(reinterpret_cast<const float2*>(&bias[((rg1 & 31) << 7) + cb]));
            float2 bv2 = __ldg(reinterpret_cast<const float2*>(&bias[((rg2 & 31) << 7) + cb]));
            *reinterpret_cast<float2*>(&out[(size_t)rg1 * 128 + cb]) =
                make_float2(c[mi][ni][0] + bv1.x, c[mi][ni][1] + bv1.y);
            *reinterpret_cast<float2*>(&out[(size_t)rg2 * 128 + cb]) =
                make_float2(c[mi][ni][2] + bv2.x, c[mi][ni][3] + bv2.y);
        }
    }
}

// ============================================================================
// Host launcher
// ============================================================================
extern "C" void kernel_launch(void* const* d_in, const int* in_sizes, int n_in,
                              void* d_out, int out_size)
{
    const float* x = nullptr;
    const float* W = nullptr;
    const float* D = nullptr;
    const float* bias = nullptr;
    for (int i = 0; i < n_in; i++) {
        if (in_sizes[i] == DIM * DIM)               x = (const float*)d_in[i];
        else if (in_sizes[i] == KBLK * KBLK * 128)  W = (const float*)d_in[i];
        else if (!D)                                D = (const float*)d_in[i];
        else                                        bias = (const float*)d_in[i];
    }
    float* out = (float*)d_out;

    static bool attr_done = false;
    if (!attr_done) {
        cudaFuncSetAttribute(k_stage1, cudaFuncAttributeMaxDynamicSharedMemorySize, S1_SMEM);
        cudaFuncSetAttribute(k_stage2, cudaFuncAttributeMaxDynamicSharedMemorySize, S2_SMEM);
        cudaFuncSetAttribute(k_stage3, cudaFuncAttributeMaxDynamicSharedMemorySize, S3_SMEM);
        attr_done = true;
    }

    k_build_F<<<(160 * 128 + 128 * 136 + 255) / 256, 256>>>();
    k_build_W2<<<(FB * 1024 * 32 + 255) / 256, 256>>>(W);

    k_stage1<<<NROWS / 128, 256, S1_SMEM>>>(x, D);
    k_stage2<<<FB * 16, 256, S2_SMEM>>>();
    k_stage3<<<NROWS / 128, 256, S3_SMEM>>>(bias, out);
}

// round 12
// speedup vs baseline: 8.8445x; 2.0032x over previous
#include <cuda_runtime.h>
#include <cstdint>

// ============================================================================
// Problem constants
// ============================================================================
#define DIM    4096
#define KBLK   32
#define FB     65           // rfft bins 0..64
#define NROWS  131072       // 4096 batch * 32 blocks
#define GRID   148          // persistent CTAs (one per SM)

// ============================================================================
// FFT-domain pipeline, tf32 tensor cores, persistent CTAs + cp.async double
// buffering. All inter-stage tensors stored PRE-ROUNDED to tf32 by producer
// epilogues so consumers can cp.async them raw.
//   Stage1: Xf = (x*D) @ F1p^T        [131072x128]@[160x128]^T (130 cols used)
//   Stage2: per-bin Of = X2 @ W2^T    65 x ([4096x64]@[64x64]^T)
//   Stage3: out = Of @ F3p^T + bias   [131072x136]@[128x136]^T (130 k used)
// ============================================================================
__device__ float g_Xf[(size_t)FB * 4096 * 64];     // [f][b][2j+c]   68.2 MB (tf32)
__device__ float g_Of[(size_t)FB * NROWS * 2];     // [f][brow][c]   68.2 MB (tf32)
__device__ float g_W2[FB * 64 * 64];               // [f][n=2i+c][k] (tf32)
__device__ float g_F1p[160 * 128];                 // [n=2f+c][u]    (tf32, 0 pad)
__device__ float g_F3p[128 * 136];                 // [t][k=2f+c]    (tf32, 0 pad)

// ============================================================================
// Helpers
// ============================================================================
__device__ __forceinline__ float tf32_rn(float v) {
    uint32_t r;
    asm("cvt.rna.tf32.f32 %0, %1;" : "=r"(r) : "f"(v));
    return __uint_as_float(r);
}

__device__ __forceinline__ uint32_t smem_u32(const void* p) {
    uint32_t a;
    asm("{ .reg .u64 t; cvta.to.shared.u64 t, %1; cvt.u32.u64 %0, t; }" : "=r"(a) : "l"(p));
    return a;
}

#define CP_ASYNC16(smem_addr, gptr) \
    asm volatile("cp.async.cg.shared.global [%0], [%1], 16;" \
                 :: "r"(smem_addr), "l"(gptr) : "memory")
#define CP_ASYNC8(smem_addr, gptr) \
    asm volatile("cp.async.ca.shared.global [%0], [%1], 8;" \
                 :: "r"(smem_addr), "l"(gptr) : "memory")
#define CP_COMMIT() asm volatile("cp.async.commit_group;" ::: "memory")
#define CP_WAIT(n)  asm volatile("cp.async.wait_group %0;" :: "n"(n) : "memory")

__device__ __forceinline__ void mma_tf32(
    float& c0, float& c1, float& c2, float& c3,
    float a0, float a1, float a2, float a3,
    float b0, float b1)
{
    asm volatile(
        "mma.sync.aligned.m16n8k8.row.col.f32.tf32.tf32.f32 "
        "{%0,%1,%2,%3}, {%4,%5,%6,%7}, {%8,%9}, {%0,%1,%2,%3};"
        : "+f"(c0), "+f"(c1), "+f"(c2), "+f"(c3)
        : "r"(__float_as_uint(a0)), "r"(__float_as_uint(a1)),
          "r"(__float_as_uint(a2)), "r"(__float_as_uint(a3)),
          "r"(__float_as_uint(b0)), "r"(__float_as_uint(b1)));
}

// ============================================================================
// Builders
// ============================================================================
__global__ void __launch_bounds__(256) k_build_F()
{
    int idx = blockIdx.x * blockDim.x + threadIdx.x;
    if (idx < 160 * 128) {
        int n = idx >> 7;
        int u = idx & 127;
        float v = 0.0f;
        if (n < 130) {
            int f = n >> 1;
            int m = (f * u) & 127;
            float th = (float)m * (1.0f / 64.0f);
            v = (n & 1) ? -sinpif(th) : cospif(th);
        }
        g_F1p[idx] = tf32_rn(v);
    } else if (idx < 160 * 128 + 128 * 136) {
        int j = idx - 160 * 128;
        int t = j / 136;
        int k = j - t * 136;
        float v = 0.0f;
        if (k < 130) {
            int f = k >> 1;
            int m = (f * t) & 127;
            float th = (float)m * (1.0f / 64.0f);
            float a  = (f == 0 || f == 64) ? 1.0f : 2.0f;
            v = ((k & 1) ? -sinpif(th) : cospif(th)) * a * (1.0f / 128.0f);
        }
        g_F3p[j] = tf32_rn(v);
    }
}

__global__ void __launch_bounds__(256) k_build_W2(const float* __restrict__ W)
{
    int wg   = (blockIdx.x * 256 + threadIdx.x) >> 5;
    int lane = threadIdx.x & 31;
    if (wg >= FB * 1024) return;
    int f = wg >> 10;
    int r = wg & 1023;
    const float* wrow = W + (size_t)r * 128;
    const float* crow = g_F1p + (2 * f) * 128;
    const float* srow = g_F1p + (2 * f + 1) * 128;   // holds -sin
    float wr = 0.0f, wi = 0.0f;
    #pragma unroll
    for (int t = 0; t < 4; t++) {
        float wv = wrow[lane + 32 * t];
        wr += wv * crow[lane + 32 * t];
        wi -= wv * srow[lane + 32 * t];
    }
    #pragma unroll
    for (int off = 16; off; off >>= 1) {
        wr += __shfl_xor_sync(0xFFFFFFFFu, wr, off);
        wi += __shfl_xor_sync(0xFFFFFFFFu, wi, off);
    }
    if (lane == 0) {
        int i = r >> 5, j = r & 31;
        float* W2f = g_W2 + (size_t)f * 4096;
        int n0 = 2 * i, n1 = 2 * i + 1, k0 = 2 * j, k1 = 2 * j + 1;
        W2f[n0 * 64 + k0] = tf32_rn( wr);
        W2f[n0 * 64 + k1] = tf32_rn(-wi);
        W2f[n1 * 64 + k0] = tf32_rn( wi);
        W2f[n1 * 64 + k1] = tf32_rn( wr);
    }
}

// ============================================================================
// Stage 1: Xf = (x*D) @ F1p^T.  Persistent CTAs, tiles of 128 rows, K=128.
// smem: A double buf [128][132] x2, B resident [160][132].
// A tile = 128 rows x 32 float4 = 4096 f4 -> 16 per thread.
// ============================================================================
#define S1_AST 132
#define S1_BST 132
#define S1_ABUF (128 * S1_AST)
#define S1_SMEM ((2 * S1_ABUF + 160 * S1_BST) * 4)   // 219648 B

__global__ void __launch_bounds__(256, 1) k_stage1(
    const float* __restrict__ x, const float* __restrict__ D)
{
    extern __shared__ __align__(16) float smem[];
    float* Bs = smem + 2 * S1_ABUF;
    const int tid = threadIdx.x;
    const uint32_t a_w = smem_u32(smem);
    const uint32_t b_w = smem_u32(Bs);

    // B fill (once): F1p rows, pre-rounded
    for (int i4 = tid; i4 < 160 * 32; i4 += 256) {
        int n = i4 >> 5, k4 = (i4 & 31) << 2;
        CP_ASYNC16(b_w + (n * S1_BST + k4) * 4, &g_F1p[n * 128 + k4]);
    }
    // prologue: A fill tile0 (16 f4 per thread; r = c>>5, u4 = (c&31)<<2)
    int t = blockIdx.x;
    {
        const float* xg = x + (size_t)t * 128 * 128;
        #pragma unroll
        for (int j = 0; j < 16; j++) {
            int c = tid + j * 256;
            int r = c >> 5, u4 = (c & 31) << 2;
            CP_ASYNC16(a_w + (r * S1_AST + u4) * 4, xg + r * 128 + u4);
        }
    }
    CP_COMMIT();

    const int lane = tid & 31;
    const int wid  = tid >> 5;
    const int wm = (wid & 1) * 64;
    const int wn = (wid >> 1) * 40;
    const int row_a = wm + (lane >> 2);
    const int row_b = wn + (lane >> 2);
    const int col_f = lane & 3;

    int buf = 0;
    while (t < 1024) {
        int tn = t + GRID;
        if (tn < 1024) {
            const float* xg = x + (size_t)tn * 128 * 128;
            const uint32_t aw = a_w + (buf ^ 1) * S1_ABUF * 4;
            #pragma unroll
            for (int j = 0; j < 16; j++) {
                int c = tid + j * 256;
                int r = c >> 5, u4 = (c & 31) << 2;
                CP_ASYNC16(aw + (r * S1_AST + u4) * 4, xg + r * 128 + u4);
            }
            CP_COMMIT();
            CP_WAIT(1);
        } else {
            CP_WAIT(0);
        }
        __syncthreads();

        float* As = smem + buf * S1_ABUF;

        // RMW: multiply by D, round to tf32 (same 16-f4-per-thread mapping)
        #pragma unroll
        for (int j = 0; j < 16; j++) {
            int c = tid + j * 256;
            int r = c >> 5, u4 = (c & 31) << 2;
            float4 v = *reinterpret_cast<float4*>(&As[r * S1_AST + u4]);
            float4 d = __ldg(reinterpret_cast<const float4*>(&D[((r & 31) << 7) + u4]));
            v.x = tf32_rn(v.x * d.x);
            v.y = tf32_rn(v.y * d.y);
            v.z = tf32_rn(v.z * d.z);
            v.w = tf32_rn(v.w * d.w);
            *reinterpret_cast<float4*>(&As[r * S1_AST + u4]) = v;
        }
        __syncthreads();

        float cacc[4][5][4];
        #pragma unroll
        for (int mi = 0; mi < 4; mi++)
            #pragma unroll
            for (int ni = 0; ni < 5; ni++)
                #pragma unroll
                for (int q = 0; q < 4; q++) cacc[mi][ni][q] = 0.0f;

        #pragma unroll
        for (int kk = 0; kk < 16; kk++) {
            float b[5][2];
            #pragma unroll
            for (int ni = 0; ni < 5; ni++) {
                const float* p = &Bs[(row_b + ni * 8) * S1_BST + kk * 8 + col_f];
                b[ni][0] = p[0];
                b[ni][1] = p[4];
            }
            #pragma unroll
            for (int mi = 0; mi < 4; mi++) {
                const float* p = &As[(row_a + mi * 16) * S1_AST + kk * 8 + col_f];
                float a0 = p[0], a1 = p[8 * S1_AST], a2 = p[4], a3 = p[8 * S1_AST + 4];
                #pragma unroll
                for (int ni = 0; ni < 5; ni++)
                    mma_tf32(cacc[mi][ni][0], cacc[mi][ni][1], cacc[mi][ni][2], cacc[mi][ni][3],
                             a0, a1, a2, a3, b[ni][0], b[ni][1]);
            }
        }

        // Epilogue: round + scatter to g_Xf[f][b][2j+c]
        const int r0 = t * 128;
        #pragma unroll
        for (int mi = 0; mi < 4; mi++) {
            int rg1 = r0 + wm + mi * 16 + (lane >> 2);
            int rg2 = rg1 + 8;
            #pragma unroll
            for (int ni = 0; ni < 5; ni++) {
                int n0 = wn + ni * 8 + 2 * (lane & 3);
                if (n0 < 130) {
                    size_t base = (size_t)(n0 >> 1) * 262144;
                    *reinterpret_cast<float2*>(
                        &g_Xf[base + (rg1 >> 5) * 64 + ((rg1 & 31) << 1)]) =
                        make_float2(tf32_rn(cacc[mi][ni][0]), tf32_rn(cacc[mi][ni][1]));
                    *reinterpret_cast<float2*>(
                        &g_Xf[base + (rg2 >> 5) * 64 + ((rg2 & 31) << 1)]) =
                        make_float2(tf32_rn(cacc[mi][ni][2]), tf32_rn(cacc[mi][ni][3]));
                }
            }
        }
        __syncthreads();
        buf ^= 1;
        t = tn;
    }
}

// ============================================================================
// Stage 2: per bin f: Of = X2[256x64] @ W2[64x64]^T.  Persistent CTAs.
// smem: A double buf [256][68] x2, B double buf [64][68] x2.
// ============================================================================
#define S2_AST 68
#define S2_ABUF (256 * S2_AST)
#define S2_BBUF (64 * S2_AST)
#define S2_SMEM ((2 * S2_ABUF + 2 * S2_BBUF) * 4)   // 174080 B
#define S2_NT   (FB * 16)                            // 1040 tiles

__global__ void __launch_bounds__(256, 1) k_stage2()
{
    extern __shared__ __align__(16) float smem[];
    const int tid = threadIdx.x;
    const uint32_t a_w = smem_u32(smem);
    const uint32_t b_w = a_w + 2 * S2_ABUF * 4;

    auto fill = [&](int tile, int buf) {
        int f  = tile >> 4;
        int b0 = (tile & 15) * 256;
        const float* Xg = g_Xf + (size_t)f * 262144 + (size_t)b0 * 64;
        const float* Wg = g_W2 + (size_t)f * 4096;
        const uint32_t aw = a_w + buf * S2_ABUF * 4;
        const uint32_t bw = b_w + buf * S2_BBUF * 4;
        // A: 256 rows x 16 f4
        #pragma unroll
        for (int j = 0; j < 16; j++) {
            int c = tid + j * 256;
            int row = c >> 4, k4 = (c & 15) << 2;
            CP_ASYNC16(aw + (row * S2_AST + k4) * 4, Xg + row * 64 + k4);
        }
        // B: 64 rows x 16 f4
        #pragma unroll
        for (int j = 0; j < 4; j++) {
            int c = tid + j * 256;
            int n = c >> 4, k4 = (c & 15) << 2;
            CP_ASYNC16(bw + (n * S2_AST + k4) * 4, Wg + n * 64 + k4);
        }
    };

    int t = blockIdx.x;
    fill(t, 0);
    CP_COMMIT();

    const int lane = tid & 31;
    const int wid  = tid >> 5;
    const int wm = (wid & 3) * 64;
    const int wn = (wid >> 2) * 32;
    const int row_a = wm + (lane >> 2);
    const int row_b = wn + (lane >> 2);
    const int col_f = lane & 3;

    int buf = 0;
    while (t < S2_NT) {
        int tn = t + GRID;
        if (tn < S2_NT) { fill(tn, buf ^ 1); CP_COMMIT(); CP_WAIT(1); }
        else CP_WAIT(0);
        __syncthreads();

        const float* Xs = smem + buf * S2_ABUF;
        const float* Ws = smem + 2 * S2_ABUF + buf * S2_BBUF;

        float cacc[4][4][4];
        #pragma unroll
        for (int mi = 0; mi < 4; mi++)
            #pragma unroll
            for (int ni = 0; ni < 4; ni++)
                #pragma unroll
                for (int q = 0; q < 4; q++) cacc[mi][ni][q] = 0.0f;

        #pragma unroll
        for (int kk = 0; kk < 8; kk++) {
            float b[4][2];
            #pragma unroll
            for (int ni = 0; ni < 4; ni++) {
                const float* p = &Ws[(row_b + ni * 8) * S2_AST + kk * 8 + col_f];
                b[ni][0] = p[0];
                b[ni][1] = p[4];
            }
            #pragma unroll
            for (int mi = 0; mi < 4; mi++) {
                const float* p = &Xs[(row_a + mi * 16) * S2_AST + kk * 8 + col_f];
                float a0 = p[0], a1 = p[8 * S2_AST], a2 = p[4], a3 = p[8 * S2_AST + 4];
                #pragma unroll
                for (int ni = 0; ni < 4; ni++)
                    mma_tf32(cacc[mi][ni][0], cacc[mi][ni][1], cacc[mi][ni][2], cacc[mi][ni][3],
                             a0, a1, a2, a3, b[ni][0], b[ni][1]);
            }
        }

        // Epilogue: round + store to g_Of[f][brow][c]
        int f  = t >> 4;
        int b0 = (t & 15) * 256;
        float* Of_f = g_Of + (size_t)f * 262144;
        #pragma unroll
        for (int mi = 0; mi < 4; mi++) {
            int b1 = b0 + wm + mi * 16 + (lane >> 2);
            int b2 = b1 + 8;
            #pragma unroll
            for (int ni = 0; ni < 4; ni++) {
                int n0 = wn + ni * 8 + 2 * (lane & 3);
                int i  = n0 >> 1;
                *reinterpret_cast<float2*>(&Of_f[(size_t)(b1 * 32 + i) * 2]) =
                    make_float2(tf32_rn(cacc[mi][ni][0]), tf32_rn(cacc[mi][ni][1]));
                *reinterpret_cast<float2*>(&Of_f[(size_t)(b2 * 32 + i) * 2]) =
                    make_float2(tf32_rn(cacc[mi][ni][2]), tf32_rn(cacc[mi][ni][3]));
            }
        }
        __syncthreads();
        buf ^= 1;
        t = tn;
    }
}

// ============================================================================
// Stage 3: out = Of @ F3p^T + bias.  Persistent CTAs, tiles of 128 rows, K=136.
// smem: A double buf [128][140] x2, B resident [128][140].
// ============================================================================
#define S3_AST 140
#define S3_ABUF (128 * S3_AST)
#define S3_SMEM ((2 * S3_ABUF + 128 * S3_AST) * 4)   // 215040 B

__global__ void __launch_bounds__(256, 1) k_stage3(
    const float* __restrict__ bias, float* __restrict__ out)
{
    extern __shared__ __align__(16) float smem[];
    float* Bs = smem + 2 * S3_ABUF;
    const int tid = threadIdx.x;
    const uint32_t a_w = smem_u32(smem);
    const uint32_t b_w = smem_u32(Bs);

    // Zero pad columns (k=130..135) of both A buffers (fills never touch them)
    if (tid < 256) {
        int row = tid & 127, bb = tid >> 7;
        float* p = smem + bb * S3_ABUF + row * S3_AST + 130;
        p[0] = 0.0f; p[1] = 0.0f; p[2] = 0.0f; p[3] = 0.0f; p[4] = 0.0f; p[5] = 0.0f;
    }

    // B fill once: F3p [t][136] -> Bs stride 140
    for (int c = tid; c < 128 * 34; c += 256) {
        int tr = c / 34, k4 = (c - tr * 34) << 2;
        CP_ASYNC16(b_w + (tr * S3_AST + k4) * 4, &g_F3p[tr * 136 + k4]);
    }
    // prologue A fill tile0: 128 rows x 65 bins, 8B each
    int t = blockIdx.x;
    {
        const uint32_t aw = a_w;
        for (int c = tid; c < 128 * FB; c += 256) {
            int r = c & 127, f = c >> 7;
            CP_ASYNC8(aw + (r * S3_AST + 2 * f) * 4,
                      g_Of + (size_t)f * 262144 + (size_t)(t * 128 + r) * 2);
        }
    }
    CP_COMMIT();

    const int lane = tid & 31;
    const int wid  = tid >> 5;
    const int wm = (wid & 1) * 64;
    const int wn = (wid >> 1) * 32;
    const int row_a = wm + (lane >> 2);
    const int row_b = wn + (lane >> 2);
    const int col_f = lane & 3;

    int buf = 0;
    while (t < 1024) {
        int tn = t + GRID;
        if (tn < 1024) {
            const uint32_t aw = a_w + (buf ^ 1) * S3_ABUF * 4;
            for (int c = tid; c < 128 * FB; c += 256) {
                int r = c & 127, f = c >> 7;
                CP_ASYNC8(aw + (r * S3_AST + 2 * f) * 4,
                          g_Of + (size_t)f * 262144 + (size_t)(tn * 128 + r) * 2);
            }
            CP_COMMIT();
            CP_WAIT(1);
        } else {
            CP_WAIT(0);
        }
        __syncthreads();

        const float* As = smem + buf * S3_ABUF;

        float cacc[4][4][4];
        #pragma unroll
        for (int mi = 0; mi < 4; mi++)
            #pragma unroll
            for (int ni = 0; ni < 4; ni++)
                #pragma unroll
                for (int q = 0; q < 4; q++) cacc[mi][ni][q] = 0.0f;

        #pragma unroll
        for (int kk = 0; kk < 17; kk++) {
            float b[4][2];
            #pragma unroll
            for (int ni = 0; ni < 4; ni++) {
                const float* p = &Bs[(row_b + ni * 8) * S3_AST + kk * 8 + col_f];
                b[ni][0] = p[0];
                b[ni][1] = p[4];
            }
            #pragma unroll
            for (int mi = 0; mi < 4; mi++) {
                const float* p = &As[(row_a + mi * 16) * S3_AST + kk * 8 + col_f];
                float a0 = p[0], a1 = p[8 * S3_AST], a2 = p[4], a3 = p[8 * S3_AST + 4];
                #pragma unroll
                for (int ni = 0; ni < 4; ni++)
                    mma_tf32(cacc[mi][ni][0], cacc[mi][ni][1], cacc[mi][ni][2], cacc[mi][ni][3],
                             a0, a1, a2, a3, b[ni][0], b[ni][1]);
            }
        }

        // Epilogue: bias + coalesced store
        const int r0 = t * 128;
        #pragma unroll
        for (int mi = 0; mi < 4; mi++) {
            int rg1 = r0 + wm + mi * 16 + (lane >> 2);
            int rg2 = rg1 + 8;
            #pragma unroll
            for (int ni = 0; ni < 4; ni++) {
                int cb = wn + ni * 8 + 2 * (lane & 3);
                float2 bv1 = __ldg(reinterpret_cast<const float2*>(&bias[((rg1 & 31) << 7) + cb]));
                float2 bv2 = __ldg(reinterpret_cast<const float2*>(&bias[((rg2 & 31) << 7) + cb]));
                *reinterpret_cast<float2*>(&out[(size_t)rg1 * 128 + cb]) =
                    make_float2(cacc[mi][ni][0] + bv1.x, cacc[mi][ni][1] + bv1.y);
                *reinterpret_cast<float2*>(&out[(size_t)rg2 * 128 + cb]) =
                    make_float2(cacc[mi][ni][2] + bv2.x, cacc[mi][ni][3] + bv2.y);
            }
        }
        __syncthreads();
        buf ^= 1;
        t = tn;
    }
}

// ============================================================================
// Host launcher
// ============================================================================
extern "C" void kernel_launch(void* const* d_in, const int* in_sizes, int n_in,
                              void* d_out, int out_size)
{
    const float* x = nullptr;
    const float* W = nullptr;
    const float* D = nullptr;
    const float* bias = nullptr;
    for (int i = 0; i < n_in; i++) {
        if (in_sizes[i] == DIM * DIM)               x = (const float*)d_in[i];
        else if (in_sizes[i] == KBLK * KBLK * 128)  W = (const float*)d_in[i];
        else if (!D)                                D = (const float*)d_in[i];
        else                                        bias = (const float*)d_in[i];
    }
    float* out = (float*)d_out;

    static bool attr_done = false;
    if (!attr_done) {
        cudaFuncSetAttribute(k_stage1, cudaFuncAttributeMaxDynamicSharedMemorySize, S1_SMEM);
        cudaFuncSetAttribute(k_stage2, cudaFuncAttributeMaxDynamicSharedMemorySize, S2_SMEM);
        cudaFuncSetAttribute(k_stage3, cudaFuncAttributeMaxDynamicSharedMemorySize, S3_SMEM);
        attr_done = true;
    }

    k_build_F<<<(160 * 128 + 128 * 136 + 255) / 256, 256>>>();
    k_build_W2<<<(FB * 1024 * 32 + 255) / 256, 256>>>(W);

    k_stage1<<<GRID, 256, S1_SMEM>>>(x, D);
    k_stage2<<<GRID, 256, S2_SMEM>>>();
    k_stage3<<<GRID, 256, S3_SMEM>>>(bias, out);
}